// round 1
// baseline (speedup 1.0000x reference)
#include <cuda_runtime.h>
#include <math.h>

// Problem constants (from reference setup_inputs: B=4096, T=8192)
#define T_LEN 8192
#define THREADS_SCAN 512
#define PER (T_LEN / THREADS_SCAN)   // 16 elements per thread
#define DISCOUNT 0.99f
#define EPS 1e-9f
#define MAX_ROWS 8192

// Scratch (no allocation allowed -> device globals)
__device__ float g_rowsum[MAX_ROWS];
__device__ float g_rowinv[MAX_ROWS];
__device__ float g_mean;

// ---------------------------------------------------------------------------
// K1: per-row reverse affine scan + per-row stats
// ret[t] = r[t] + g[t]*ret[t+1],  g[t] = DISCOUNT*(1-done[t])
// Reversed index s = T-1-t turns this into a forward recurrence y = b + a*y.
// Thread j owns reversed positions [j*PER, (j+1)*PER) = original t range
// [T - PER*(j+1), T - PER*j), a contiguous 64B chunk -> 4x LDG.128.
// ---------------------------------------------------------------------------
__global__ __launch_bounds__(THREADS_SCAN)
void scan_kernel(const float* __restrict__ rew,
                 const float* __restrict__ done,
                 float* __restrict__ out)
{
    const int b = blockIdx.x;
    const size_t rowoff = (size_t)b * T_LEN;
    const float* r = rew + rowoff;
    const float* d = done + rowoff;
    float* o = out + rowoff;

    const int j = threadIdx.x;
    const int tbase = T_LEN - PER * (j + 1);

    float rv[PER];
    float av[PER];

#pragma unroll
    for (int k = 0; k < PER / 4; k++) {
        float4 rr = *(const float4*)(r + tbase + 4 * k);
        float4 dd = *(const float4*)(d + tbase + 4 * k);
        rv[4 * k + 0] = rr.x; av[4 * k + 0] = DISCOUNT * (1.0f - dd.x);
        rv[4 * k + 1] = rr.y; av[4 * k + 1] = DISCOUNT * (1.0f - dd.y);
        rv[4 * k + 2] = rr.z; av[4 * k + 2] = DISCOUNT * (1.0f - dd.z);
        rv[4 * k + 3] = rr.w; av[4 * k + 3] = DISCOUNT * (1.0f - dd.w);
    }

    // Compose the chunk's affine map: apply elements in s-ascending order
    // (t descending: i = PER-1 .. 0). New element applied after current map:
    //   y_out = a*(A*y + B) + b  ->  A <- a*A, B <- a*B + b
    float A = 1.0f, Bc = 0.0f;
#pragma unroll
    for (int i = PER - 1; i >= 0; i--) {
        Bc = fmaf(av[i], Bc, rv[i]);
        A  = av[i] * A;
    }

    // Block-wide inclusive affine scan (Hillis-Steele, 9 steps for 512)
    __shared__ float sA[THREADS_SCAN];
    __shared__ float sB[THREADS_SCAN];
    sA[j] = A; sB[j] = Bc;
    __syncthreads();
#pragma unroll
    for (int off = 1; off < THREADS_SCAN; off <<= 1) {
        float a2 = sA[j], b2 = sB[j];
        float a1 = 1.0f, b1 = 0.0f;
        const bool has = (j >= off);
        if (has) { a1 = sA[j - off]; b1 = sB[j - off]; }
        __syncthreads();
        if (has) { sA[j] = a2 * a1; sB[j] = fmaf(a2, b1, b2); }
        __syncthreads();
    }
    // Incoming carry for thread j = inclusive result of threads [0..j-1]
    // applied to y0 = 0  ->  just the B component.
    const float carry = (j == 0) ? 0.0f : sB[j - 1];
    __syncthreads();   // about to reuse sA/sB for reductions

    // Rematerialize outputs from registers
    float y = carry;
    float ov[PER];
    float lsum = 0.0f, lsq = 0.0f;
#pragma unroll
    for (int i = PER - 1; i >= 0; i--) {
        y = fmaf(av[i], y, rv[i]);
        ov[i] = y;
        lsum += y;
        lsq  = fmaf(y, y, lsq);
    }

#pragma unroll
    for (int k = 0; k < PER / 4; k++) {
        float4 w;
        w.x = ov[4 * k + 0];
        w.y = ov[4 * k + 1];
        w.z = ov[4 * k + 2];
        w.w = ov[4 * k + 3];
        *(float4*)(o + tbase + 4 * k) = w;
    }

    // Deterministic block reduction of sum / sumsq
    sA[j] = lsum; sB[j] = lsq;
    __syncthreads();
#pragma unroll
    for (int off = THREADS_SCAN / 2; off > 0; off >>= 1) {
        if (j < off) {
            sA[j] += sA[j + off];
            sB[j] += sB[j + off];
        }
        __syncthreads();
    }
    if (j == 0) {
        const float bsum = sA[0];
        const float bsq  = sB[0];
        g_rowsum[b] = bsum;
        float var = (bsq - bsum * bsum * (1.0f / T_LEN)) * (1.0f / (T_LEN - 1));
        var = fmaxf(var, 0.0f);
        const float sd = sqrtf(var);
        g_rowinv[b] = 1.0f / (sd + EPS);
    }
}

// ---------------------------------------------------------------------------
// K2: deterministic reduction of row sums -> global mean
// ---------------------------------------------------------------------------
__global__ __launch_bounds__(1024)
void mean_kernel(int n_rows)
{
    __shared__ double sd[1024];
    const int j = threadIdx.x;
    double acc = 0.0;
    for (int i = j; i < n_rows; i += 1024)
        acc += (double)g_rowsum[i];
    sd[j] = acc;
    __syncthreads();
#pragma unroll
    for (int off = 512; off > 0; off >>= 1) {
        if (j < off) sd[j] += sd[j + off];
        __syncthreads();
    }
    if (j == 0)
        g_mean = (float)(sd[0] / ((double)n_rows * (double)T_LEN));
}

// ---------------------------------------------------------------------------
// K3: in-place normalize  out = (out - mean) * rowinv[b]
// ---------------------------------------------------------------------------
__global__ __launch_bounds__(256)
void norm_kernel(float* __restrict__ out, int n4)
{
    const float mean = g_mean;
    int i = blockIdx.x * blockDim.x + threadIdx.x;
    if (i >= n4) return;
    float4 v = ((const float4*)out)[i];
    const int row = (i * 4) >> 13;           // /T_LEN, T=8192
    const float inv = g_rowinv[row];
    v.x = (v.x - mean) * inv;
    v.y = (v.y - mean) * inv;
    v.z = (v.z - mean) * inv;
    v.w = (v.w - mean) * inv;
    ((float4*)out)[i] = v;
}

extern "C" void kernel_launch(void* const* d_in, const int* in_sizes, int n_in,
                              void* d_out, int out_size)
{
    const float* rewards = (const float*)d_in[0];
    const float* dones   = (const float*)d_in[1];
    float* out = (float*)d_out;

    const int n = in_sizes[0];
    const int B = n / T_LEN;

    scan_kernel<<<B, THREADS_SCAN>>>(rewards, dones, out);
    mean_kernel<<<1, 1024>>>(B);
    const int n4 = n / 4;
    norm_kernel<<<(n4 + 255) / 256, 256>>>(out, n4);
}